// round 7
// baseline (speedup 1.0000x reference)
#include <cuda_runtime.h>
#include <cuda_bf16.h>
#include <cstdint>
#include <cstddef>

// ---------------- problem constants ----------------
#define BATCH 32768
#define PDIM  24
#define CIN   64
#define COUT  64
#define NORB  24
#define KDIM  1536   // P*C_IN   (k = j*64 + c)
#define NDIM  1536   // P*C_OUT  (n = i*64 + o)

// ---------------- GEMM tiling ----------------
#define M_T 256
#define N_T 128
#define KC  64                          // bf16 per K-chunk = 128 bytes per row
#define CHUNKS_PER_PASS (KDIM / KC)     // 24
#define NPASS 3                         // xh*Bh + xl*Bh + xh*Bl
#define NCHUNK (NPASS * CHUNKS_PER_PASS) // 72
#define NSTAGE 3

#define A_BYTES (M_T * 128)             // 32 KB per stage
#define B_BYTES (N_T * 128)             // 16 KB per stage
#define STAGE_BYTES (A_BYTES + B_BYTES) // 48 KB
#define SMEM_BYTES (NSTAGE * STAGE_BYTES) // 147456 < 227KB

#define NTILE_N (NDIM / N_T)            // 12
#define NCTAS   ((BATCH / M_T) * NTILE_N) // 1536

// ---------------- scratch (device globals; no cudaMalloc allowed) ----------
__device__ __align__(1024) __nv_bfloat16 g_Xh[(size_t)BATCH * KDIM];
__device__ __align__(1024) __nv_bfloat16 g_Xl[(size_t)BATCH * KDIM];
__device__ __align__(1024) __nv_bfloat16 g_Bh[(size_t)NDIM * KDIM];
__device__ __align__(1024) __nv_bfloat16 g_Bl[(size_t)NDIM * KDIM];
__device__ int g_is64;

// ---------------- PTX helpers (base-PTX only: no tcgen05/TMA) --------------
static __device__ __forceinline__ uint32_t smem_u32(const void* p) {
    uint32_t a;
    asm("{ .reg .u64 t; cvta.to.shared.u64 t, %1; cvt.u32.u64 %0, t; }"
        : "=r"(a) : "l"(p));
    return a;
}

#define CP_ASYNC16(dst, src) \
    asm volatile("cp.async.cg.shared.global [%0], [%1], 16;" \
                 :: "r"(dst), "l"(src) : "memory")
#define CP_COMMIT() asm volatile("cp.async.commit_group;" ::: "memory")
#define CP_WAIT1()  asm volatile("cp.async.wait_group 1;" ::: "memory")
#define CP_WAIT0()  asm volatile("cp.async.wait_group 0;" ::: "memory")

#define LDSM_X4(r, addr) \
    asm volatile("ldmatrix.sync.aligned.m8n8.x4.shared.b16 {%0,%1,%2,%3}, [%4];" \
                 : "=r"((r)[0]), "=r"((r)[1]), "=r"((r)[2]), "=r"((r)[3]) \
                 : "r"(addr))

#define MMA16816(d, a, b) \
    asm volatile("mma.sync.aligned.m16n8k16.row.col.f32.bf16.bf16.f32 " \
                 "{%0,%1,%2,%3}, {%4,%5,%6,%7}, {%8,%9}, {%0,%1,%2,%3};" \
                 : "+f"((d)[0]), "+f"((d)[1]), "+f"((d)[2]), "+f"((d)[3]) \
                 : "r"((a)[0]), "r"((a)[1]), "r"((a)[2]), "r"((a)[3]), \
                   "r"((b)[0]), "r"((b)[1]))

// ---------------- prep kernels ----------------

// pair_orbit may be int64 (reference requests it) or int32 (x64 disabled).
// Little-endian int64 viewed as int32 alternates [value, 0] (values in
// [0,24)): all 288 odd words of the first 576 int32s zero -> int64.
__global__ void detect_kernel(const int* __restrict__ po32) {
    __shared__ int nonzero;
    if (threadIdx.x == 0) nonzero = 0;
    __syncthreads();
    int idx = 2 * threadIdx.x + 1;     // 1,3,...,575
    if (po32[idx] != 0) atomicAdd(&nonzero, 1);
    __syncthreads();
    if (threadIdx.x == 0) g_is64 = (nonzero == 0) ? 1 : 0;
}

// B[n,k] = W[o, c, orbit(i,j)], n=i*64+o, k=j*64+c ; split to bf16 hi/lo
__global__ void build_b_kernel(const float* __restrict__ w, const void* __restrict__ po) {
    int idx = blockIdx.x * blockDim.x + threadIdx.x;   // exact grid: NDIM*KDIM
    int n = idx / KDIM, k = idx - n * KDIM;
    int i = n >> 6, o = n & 63;
    int j = k >> 6, c = k & 63;
    int orb;
    if (g_is64) orb = (int)((const long long*)po)[i * PDIM + j];
    else        orb = ((const int*)po)[i * PDIM + j];
    float wv = w[(o * CIN + c) * NORB + orb];
    __nv_bfloat16 hi = __float2bfloat16(wv);
    float lo = wv - __bfloat162float(hi);   // exact
    g_Bh[idx] = hi;
    g_Bl[idx] = __float2bfloat16(lo);
}

// x fp32 -> (xh, xl) bf16 split
__global__ void convert_x_kernel(const float4* __restrict__ x) {
    int idx = blockIdx.x * blockDim.x + threadIdx.x;   // exact grid: BATCH*KDIM/4
    float4 v = x[idx];
    __nv_bfloat16 h0 = __float2bfloat16(v.x);
    __nv_bfloat16 h1 = __float2bfloat16(v.y);
    __nv_bfloat16 h2 = __float2bfloat16(v.z);
    __nv_bfloat16 h3 = __float2bfloat16(v.w);
    __nv_bfloat162* ph = (__nv_bfloat162*)g_Xh;
    __nv_bfloat162* pl = (__nv_bfloat162*)g_Xl;
    __nv_bfloat162 a, b;
    a.x = h0; a.y = h1; b.x = h2; b.y = h3;
    ph[2 * idx] = a; ph[2 * idx + 1] = b;
    a.x = __float2bfloat16(v.x - __bfloat162float(h0));
    a.y = __float2bfloat16(v.y - __bfloat162float(h1));
    b.x = __float2bfloat16(v.z - __bfloat162float(h2));
    b.y = __float2bfloat16(v.w - __bfloat162float(h3));
    pl[2 * idx] = a; pl[2 * idx + 1] = b;
}

// ---------------- GEMM ----------------
// Stage layout: A tile 256 rows x 128B (swizzled), then B tile 128 rows x 128B.
// Swizzle closed form for 128B rows: addr = row*128 + (cb ^ ((row&7)*16))
static __device__ __forceinline__ void load_chunk(int t, uint32_t stage,
                                                  int m0, int n0, int tid) {
    int pass = t / CHUNKS_PER_PASS;
    int kk = (t - pass * CHUNKS_PER_PASS) * KC;
    const __nv_bfloat16* Asrc = (pass == 1) ? g_Xl : g_Xh;
    const __nv_bfloat16* Bsrc = (pass == 2) ? g_Bl : g_Bh;
    const char* Ab = (const char*)Asrc + ((size_t)m0 * KDIM + kk) * 2;
    const char* Bb = (const char*)Bsrc + ((size_t)n0 * KDIM + kk) * 2;
#pragma unroll
    for (int it = 0; it < 4; ++it) {              // A: 2048 x 16B
        int idx = it * 512 + tid;
        int row = idx >> 3, cb = (idx & 7) * 16;
        uint32_t sw = (uint32_t)(row * 128 + (cb ^ ((row & 7) * 16)));
        CP_ASYNC16(stage + sw, Ab + (size_t)row * (KDIM * 2) + cb);
    }
#pragma unroll
    for (int it = 0; it < 2; ++it) {              // B: 1024 x 16B
        int idx = it * 512 + tid;
        int row = idx >> 3, cb = (idx & 7) * 16;
        uint32_t sw = (uint32_t)(row * 128 + (cb ^ ((row & 7) * 16)));
        CP_ASYNC16(stage + A_BYTES + sw, Bb + (size_t)row * (KDIM * 2) + cb);
    }
}

__global__ void __launch_bounds__(512, 1)
gemm_kernel(const float* __restrict__ bias, float* __restrict__ out) {
    extern __shared__ __align__(1024) char smem[];
    const uint32_t sbase = smem_u32(smem);
    const int tid = threadIdx.x;
    const int wid = tid >> 5;
    const int lane = tid & 31;
    const int wm = wid >> 2;          // 0..3  (m warp index, 64 rows each)
    const int wn = wid & 3;           // 0..3  (n warp index, 32 cols each)

    const int m0 = (int)(blockIdx.x / NTILE_N) * M_T;
    const int n0 = (int)(blockIdx.x % NTILE_N) * N_T;

    float acc[4][4][4];               // [mt][nt][4] fp32
#pragma unroll
    for (int a = 0; a < 4; ++a)
#pragma unroll
        for (int b = 0; b < 4; ++b)
#pragma unroll
            for (int c = 0; c < 4; ++c) acc[a][b][c] = 0.0f;

    // per-lane bias (col mod 64): o = (wn*32 + nt*8 + (lane&3)*2) & 63
    float2 bv[4];
#pragma unroll
    for (int nt = 0; nt < 4; ++nt) {
        int o = (wn * 32 + nt * 8 + (lane & 3) * 2) & 63;
        bv[nt].x = bias[o];
        bv[nt].y = bias[o + 1];
    }

    // per-lane ldmatrix addressing (verified against PTX mma fragment layouts)
    const int swz = (lane & 7) * 16;                  // row&7 == lane&7 (A and B)
    const int ah  = (lane >> 4) * 16;                 // A: k-half select (16B)
    const int bh  = ((lane >> 3) & 1) * 16;           // B: k-half select
    uint32_t pA[4], pB[2];
#pragma unroll
    for (int mt = 0; mt < 4; ++mt) {
        int row = wm * 64 + mt * 16 + (lane & 15);
        pA[mt] = row * 128;
    }
#pragma unroll
    for (int pr = 0; pr < 2; ++pr) {
        int row = wn * 32 + pr * 16 + ((lane >> 4) * 8) + (lane & 7);
        pB[pr] = A_BYTES + row * 128;
    }

    // prologue: stages 0 and 1
    load_chunk(0, sbase, m0, n0, tid);               CP_COMMIT();
    load_chunk(1, sbase + STAGE_BYTES, m0, n0, tid); CP_COMMIT();

    for (int t = 0; t < NCHUNK; ++t) {
        if (t + 2 < NCHUNK) { CP_WAIT1(); } else { CP_WAIT0(); }
        __syncthreads();
        if (t + 2 < NCHUNK) {
            load_chunk(t + 2, sbase + ((t + 2) % NSTAGE) * STAGE_BYTES, m0, n0, tid);
            CP_COMMIT();
        }

        const uint32_t stg = sbase + (t % NSTAGE) * STAGE_BYTES;
#pragma unroll
        for (int ks = 0; ks < 4; ++ks) {
            uint32_t af[4][4], bf[4][2], tmp[4];
            const uint32_t cbA = (uint32_t)((ks * 32 + ah) ^ swz);
            const uint32_t cbB = (uint32_t)((ks * 32 + bh) ^ swz);
#pragma unroll
            for (int mt = 0; mt < 4; ++mt)
                LDSM_X4(af[mt], stg + pA[mt] + cbA);
#pragma unroll
            for (int pr = 0; pr < 2; ++pr) {
                LDSM_X4(tmp, stg + pB[pr] + cbB);
                bf[2 * pr][0] = tmp[0]; bf[2 * pr][1] = tmp[1];
                bf[2 * pr + 1][0] = tmp[2]; bf[2 * pr + 1][1] = tmp[3];
            }
#pragma unroll
            for (int mt = 0; mt < 4; ++mt)
#pragma unroll
                for (int nt = 0; nt < 4; ++nt)
                    MMA16816(acc[mt][nt], af[mt], bf[nt]);
        }
        // stage reuse is fenced by the next iteration's wait + __syncthreads
    }

    // epilogue: c0,c1 -> row lane/4 ; c2,c3 -> row lane/4+8 ; col = (lane&3)*2
#pragma unroll
    for (int mt = 0; mt < 4; ++mt) {
        const int r0 = m0 + wm * 64 + mt * 16 + (lane >> 2);
#pragma unroll
        for (int nt = 0; nt < 4; ++nt) {
            const int col = n0 + wn * 32 + nt * 8 + (lane & 3) * 2;
            float2 v0, v1;
            v0.x = acc[mt][nt][0] + bv[nt].x;
            v0.y = acc[mt][nt][1] + bv[nt].y;
            v1.x = acc[mt][nt][2] + bv[nt].x;
            v1.y = acc[mt][nt][3] + bv[nt].y;
            *(float2*)(out + (size_t)r0 * NDIM + col) = v0;
            *(float2*)(out + (size_t)(r0 + 8) * NDIM + col) = v1;
        }
    }
}

// ---------------- launch ----------------
extern "C" void kernel_launch(void* const* d_in, const int* in_sizes, int n_in,
                              void* d_out, int out_size) {
    (void)in_sizes; (void)n_in; (void)out_size;
    const float* x    = (const float*)d_in[0];
    const float* w    = (const float*)d_in[1];
    const float* bias = (const float*)d_in[2];
    const void*  po   = d_in[3];
    float* out = (float*)d_out;

    // Idempotent, not a stream op (legal during graph capture), no static guard.
    cudaFuncSetAttribute(gemm_kernel,
                         cudaFuncAttributeMaxDynamicSharedMemorySize, SMEM_BYTES);

    detect_kernel<<<1, 288>>>((const int*)po);
    build_b_kernel<<<(NDIM * KDIM) / 256, 256>>>(w, po);
    convert_x_kernel<<<(BATCH * KDIM / 4) / 256, 256>>>((const float4*)x);
    gemm_kernel<<<NCTAS, 512, SMEM_BYTES>>>(bias, out);
}

// round 16
// speedup vs baseline: 1.5016x; 1.5016x over previous
#include <cuda_runtime.h>
#include <cuda_fp16.h>
#include <cstdint>
#include <cstddef>

// ---------------- problem constants ----------------
#define BATCH 32768
#define PDIM  24
#define CIN   64
#define COUT  64
#define NORB  24
#define KDIM  1536   // P*C_IN   (k = j*64 + c)
#define NDIM  1536   // P*C_OUT  (n = i*64 + o)

// ---------------- GEMM tiling ----------------
#define M_T 256
#define N_T 128
#define KC  64                          // fp16 per K-chunk = 128 bytes per row
#define CHUNKS_PER_PASS (KDIM / KC)     // 24
#define NPASS 2                         // xh*Bh + xl*Bh   (fp16 split)
#define NCHUNK (NPASS * CHUNKS_PER_PASS) // 48
#define NSTAGE 4

#define A_BYTES (M_T * 128)             // 32 KB per stage
#define B_BYTES (N_T * 128)             // 16 KB per stage
#define STAGE_BYTES (A_BYTES + B_BYTES) // 48 KB
#define SMEM_BYTES (NSTAGE * STAGE_BYTES) // 196608 <= 227KB opt-in

#define NTILE_N (NDIM / N_T)            // 12
#define NCTAS   ((BATCH / M_T) * NTILE_N) // 1536

// ---------------- scratch (device globals; no cudaMalloc allowed) ----------
__device__ __align__(1024) __half g_Xh[(size_t)BATCH * KDIM];
__device__ __align__(1024) __half g_Xl[(size_t)BATCH * KDIM];
__device__ __align__(1024) __half g_Bh[(size_t)NDIM * KDIM];
__device__ int g_is64;

// ---------------- PTX helpers (base-PTX only) ----------------
static __device__ __forceinline__ uint32_t smem_u32(const void* p) {
    uint32_t a;
    asm("{ .reg .u64 t; cvta.to.shared.u64 t, %1; cvt.u32.u64 %0, t; }"
        : "=r"(a) : "l"(p));
    return a;
}

#define CP_ASYNC16(dst, src) \
    asm volatile("cp.async.cg.shared.global [%0], [%1], 16;" \
                 :: "r"(dst), "l"(src) : "memory")
#define CP_COMMIT() asm volatile("cp.async.commit_group;" ::: "memory")
#define CP_WAIT2()  asm volatile("cp.async.wait_group 2;" ::: "memory")
#define CP_WAIT1()  asm volatile("cp.async.wait_group 1;" ::: "memory")
#define CP_WAIT0()  asm volatile("cp.async.wait_group 0;" ::: "memory")

#define LDSM_X4(r, addr) \
    asm volatile("ldmatrix.sync.aligned.m8n8.x4.shared.b16 {%0,%1,%2,%3}, [%4];" \
                 : "=r"((r)[0]), "=r"((r)[1]), "=r"((r)[2]), "=r"((r)[3]) \
                 : "r"(addr))

#define MMA16816(d, a, b) \
    asm volatile("mma.sync.aligned.m16n8k16.row.col.f32.f16.f16.f32 " \
                 "{%0,%1,%2,%3}, {%4,%5,%6,%7}, {%8,%9}, {%0,%1,%2,%3};" \
                 : "+f"((d)[0]), "+f"((d)[1]), "+f"((d)[2]), "+f"((d)[3]) \
                 : "r"((a)[0]), "r"((a)[1]), "r"((a)[2]), "r"((a)[3]), \
                   "r"((b)[0]), "r"((b)[1]))

// ---------------- prep kernels ----------------

// pair_orbit may be int64 (reference requests it) or int32 (x64 disabled).
__global__ void detect_kernel(const int* __restrict__ po32) {
    __shared__ int nonzero;
    if (threadIdx.x == 0) nonzero = 0;
    __syncthreads();
    int idx = 2 * threadIdx.x + 1;     // 1,3,...,575
    if (po32[idx] != 0) atomicAdd(&nonzero, 1);
    __syncthreads();
    if (threadIdx.x == 0) g_is64 = (nonzero == 0) ? 1 : 0;
}

// B[n,k] = fp16(W[o, c, orbit(i,j)]), n=i*64+o, k=j*64+c
__global__ void build_b_kernel(const float* __restrict__ w, const void* __restrict__ po) {
    int idx = blockIdx.x * blockDim.x + threadIdx.x;   // exact grid: NDIM*KDIM
    int n = idx / KDIM, k = idx - n * KDIM;
    int i = n >> 6, o = n & 63;
    int j = k >> 6, c = k & 63;
    int orb;
    if (g_is64) orb = (int)((const long long*)po)[i * PDIM + j];
    else        orb = ((const int*)po)[i * PDIM + j];
    g_Bh[idx] = __float2half(w[(o * CIN + c) * NORB + orb]);
}

// x fp32 -> (xh, xl) fp16 split: xh = fp16(x), xl = fp16(x - xh)
__global__ void convert_x_kernel(const float4* __restrict__ x) {
    int idx = blockIdx.x * blockDim.x + threadIdx.x;   // exact grid: BATCH*KDIM/4
    float4 v = x[idx];
    __half h0 = __float2half(v.x);
    __half h1 = __float2half(v.y);
    __half h2 = __float2half(v.z);
    __half h3 = __float2half(v.w);
    __half2* ph = (__half2*)g_Xh;
    __half2* pl = (__half2*)g_Xl;
    __half2 a, b;
    a.x = h0; a.y = h1; b.x = h2; b.y = h3;
    ph[2 * idx] = a; ph[2 * idx + 1] = b;
    a.x = __float2half(v.x - __half2float(h0));
    a.y = __float2half(v.y - __half2float(h1));
    b.x = __float2half(v.z - __half2float(h2));
    b.y = __float2half(v.w - __half2float(h3));
    pl[2 * idx] = a; pl[2 * idx + 1] = b;
}

// ---------------- GEMM ----------------
// Stage layout: A tile 256 rows x 128B (swizzled), then B tile 128 rows x 128B.
// Swizzle closed form for 128B rows: addr = row*128 + (cb ^ ((row&7)*16))
static __device__ __forceinline__ void load_chunk(int t, uint32_t stage,
                                                  int m0, int n0, int tid) {
    int pass = t / CHUNKS_PER_PASS;
    int kk = (t - pass * CHUNKS_PER_PASS) * KC;
    const __half* Asrc = pass ? g_Xl : g_Xh;
    const char* Ab = (const char*)Asrc + ((size_t)m0 * KDIM + kk) * 2;
    const char* Bb = (const char*)g_Bh + ((size_t)n0 * KDIM + kk) * 2;
#pragma unroll
    for (int it = 0; it < 8; ++it) {              // A: 2048 x 16B, 256 threads
        int idx = it * 256 + tid;
        int row = idx >> 3, cb = (idx & 7) * 16;
        uint32_t sw = (uint32_t)(row * 128 + (cb ^ ((row & 7) * 16)));
        CP_ASYNC16(stage + sw, Ab + (size_t)row * (KDIM * 2) + cb);
    }
#pragma unroll
    for (int it = 0; it < 4; ++it) {              // B: 1024 x 16B
        int idx = it * 256 + tid;
        int row = idx >> 3, cb = (idx & 7) * 16;
        uint32_t sw = (uint32_t)(row * 128 + (cb ^ ((row & 7) * 16)));
        CP_ASYNC16(stage + A_BYTES + sw, Bb + (size_t)row * (KDIM * 2) + cb);
    }
}

__global__ void __launch_bounds__(256, 1)
gemm_kernel(const float* __restrict__ bias, float* __restrict__ out) {
    extern __shared__ __align__(1024) char smem[];
    const uint32_t sbase = smem_u32(smem);
    const int tid = threadIdx.x;
    const int wid = tid >> 5;
    const int lane = tid & 31;
    const int wm = wid >> 1;          // 0..3  (m warp index, 64 rows each)
    const int wn = wid & 1;           // 0..1  (n warp index, 64 cols each)

    const int m0 = (int)(blockIdx.x / NTILE_N) * M_T;
    const int n0 = (int)(blockIdx.x % NTILE_N) * N_T;

    float acc[4][8][4];               // warp tile 64x64: [mt][nt][4]
#pragma unroll
    for (int a = 0; a < 4; ++a)
#pragma unroll
        for (int b = 0; b < 8; ++b)
#pragma unroll
            for (int c = 0; c < 4; ++c) acc[a][b][c] = 0.0f;

    // per-lane bias (col mod 64): o = (wn*64 + nt*8 + (lane&3)*2) & 63
    float2 bv[8];
#pragma unroll
    for (int nt = 0; nt < 8; ++nt) {
        int o = (wn * 64 + nt * 8 + (lane & 3) * 2) & 63;
        bv[nt].x = bias[o];
        bv[nt].y = bias[o + 1];
    }

    // per-lane ldmatrix addressing (identical lane math to the proven kernel)
    const int swz = (lane & 7) * 16;                  // row&7 == lane&7 (A and B)
    const int ah  = (lane >> 4) * 16;                 // A: k-half select (16B)
    const int bh  = ((lane >> 3) & 1) * 16;           // B: k-half select
    uint32_t pA[4], pB[4];
#pragma unroll
    for (int mt = 0; mt < 4; ++mt) {
        int row = wm * 64 + mt * 16 + (lane & 15);
        pA[mt] = row * 128;
    }
#pragma unroll
    for (int pr = 0; pr < 4; ++pr) {
        int row = wn * 64 + pr * 16 + ((lane >> 4) * 8) + (lane & 7);
        pB[pr] = A_BYTES + row * 128;
    }

    // prologue: stages 0..2
    load_chunk(0, sbase, m0, n0, tid);                   CP_COMMIT();
    load_chunk(1, sbase + STAGE_BYTES, m0, n0, tid);     CP_COMMIT();
    load_chunk(2, sbase + 2 * STAGE_BYTES, m0, n0, tid); CP_COMMIT();

    for (int t = 0; t < NCHUNK; ++t) {
        if (t <= NCHUNK - 3)      { CP_WAIT2(); }
        else if (t == NCHUNK - 2) { CP_WAIT1(); }
        else                      { CP_WAIT0(); }
        __syncthreads();
        if (t + 3 < NCHUNK) {
            load_chunk(t + 3, sbase + ((t + 3) % NSTAGE) * STAGE_BYTES, m0, n0, tid);
            CP_COMMIT();
        }

        const uint32_t stg = sbase + (t % NSTAGE) * STAGE_BYTES;
#pragma unroll
        for (int ks = 0; ks < 4; ++ks) {
            uint32_t af[4][4], bf[8][2], tmp[4];
            const uint32_t cbA = (uint32_t)((ks * 32 + ah) ^ swz);
            const uint32_t cbB = (uint32_t)((ks * 32 + bh) ^ swz);
#pragma unroll
            for (int mt = 0; mt < 4; ++mt)
                LDSM_X4(af[mt], stg + pA[mt] + cbA);
#pragma unroll
            for (int pr = 0; pr < 4; ++pr) {
                LDSM_X4(tmp, stg + pB[pr] + cbB);
                bf[2 * pr][0] = tmp[0]; bf[2 * pr][1] = tmp[1];
                bf[2 * pr + 1][0] = tmp[2]; bf[2 * pr + 1][1] = tmp[3];
            }
#pragma unroll
            for (int mt = 0; mt < 4; ++mt)
#pragma unroll
                for (int nt = 0; nt < 8; ++nt)
                    MMA16816(acc[mt][nt], af[mt], bf[nt]);
        }
        // stage reuse is fenced by the next iteration's wait + __syncthreads
    }

    // epilogue: c0,c1 -> row lane/4 ; c2,c3 -> row lane/4+8 ; col = (lane&3)*2
#pragma unroll
    for (int mt = 0; mt < 4; ++mt) {
        const int r0 = m0 + wm * 64 + mt * 16 + (lane >> 2);
#pragma unroll
        for (int nt = 0; nt < 8; ++nt) {
            const int col = n0 + wn * 64 + nt * 8 + (lane & 3) * 2;
            float2 v0, v1;
            v0.x = acc[mt][nt][0] + bv[nt].x;
            v0.y = acc[mt][nt][1] + bv[nt].y;
            v1.x = acc[mt][nt][2] + bv[nt].x;
            v1.y = acc[mt][nt][3] + bv[nt].y;
            *(float2*)(out + (size_t)r0 * NDIM + col) = v0;
            *(float2*)(out + (size_t)(r0 + 8) * NDIM + col) = v1;
        }
    }
}

// ---------------- launch ----------------
extern "C" void kernel_launch(void* const* d_in, const int* in_sizes, int n_in,
                              void* d_out, int out_size) {
    (void)in_sizes; (void)n_in; (void)out_size;
    const float* x    = (const float*)d_in[0];
    const float* w    = (const float*)d_in[1];
    const float* bias = (const float*)d_in[2];
    const void*  po   = d_in[3];
    float* out = (float*)d_out;

    cudaFuncSetAttribute(gemm_kernel,
                         cudaFuncAttributeMaxDynamicSharedMemorySize, SMEM_BYTES);

    detect_kernel<<<1, 288>>>((const int*)po);
    build_b_kernel<<<(NDIM * KDIM) / 256, 256>>>(w, po);
    convert_x_kernel<<<(BATCH * KDIM / 4) / 256, 256>>>((const float4*)x);
    gemm_kernel<<<NCTAS, 256, SMEM_BYTES>>>(bias, out);
}